// round 16
// baseline (speedup 1.0000x reference)
#include <cuda_runtime.h>
#include <cuda_bf16.h>
#include <cstdint>

// ============================================================================
// PathwayPredictor, mma.sync bf16-split, 2 molecules/CTA, 128 threads,
// M=32 per warp, 3 CTAs/SM (smem 74.6KB).
// GEMM1: X(pre-split embed table, LDG.64 frags) @ W1^T [K=80, 3-term]
// GEMM2: A(JIT gmem frags) @ H1(smem, hi only)         [K=64, 1-term bf16]
// GEMM3: D2 (in-register chain) @ W2^T (PRELOADED)     [K=80, 3-term]
// W1 and W2 in separate smem regions (both loaded in phase 0) -> no W overwrite
// barrier. Per-molecule warp-pair named barriers; only ONE CTA-wide sync.
// pool collapse: y = colsum(A) @ relu(D3+b2); per-pair-leader head.
// Single merged prep kernel (W split + embed split).
// ============================================================================

#define SWW 44   // W row stride, u32 words (88 bf16)
#define SHW 36   // H row stride, u32 words (72 bf16)

// smem float indices (ALL regions disjoint -- no overlays)
#define B1I 0       // b1 padded [72]
#define B2I 72      // b2 padded [72]
#define BPI 144     // bp [16]
#define CSP 160     // colsum partials [4][128]
#define CSI 672     // colsum [128] (mol-major)
#define PLI 800     // pool partials [4][72]
#define YI  1088    // y [2][72]
// byte offsets
#define OFF_H  4928     // 2 x (72x72 hi) b16 = 20736
#define OFF_W1 25664    // 72x88 hi + lo = 25344
#define OFF_W2 51008    // 72x88 hi + lo = 25344
#define SMEM_BYTES 76352
#define WTILE 12672
#define HTILE 10368

__device__ __align__(16) unsigned char g_wt[2][2][WTILE];   // [layer][hi/lo]
__device__ __align__(16) uint32_t g_emb[10000][80];         // {hi,lo} word pairs

// ---------------- helpers ----------------
__device__ __forceinline__ uint16_t bf16h(float v) {
    __nv_bfloat16 b = __float2bfloat16(v);
    return *reinterpret_cast<uint16_t*>(&b);
}
__device__ __forceinline__ void split2(float v, uint16_t& h, uint16_t& l) {
    __nv_bfloat16 bh = __float2bfloat16(v);
    h = *reinterpret_cast<uint16_t*>(&bh);
    __nv_bfloat16 bl = __float2bfloat16(v - __bfloat162float(bh));
    l = *reinterpret_cast<uint16_t*>(&bl);
}
__device__ __forceinline__ uint32_t packb(float2 v) {   // lo16=bf16(v.x), hi16=bf16(v.y)
    uint32_t r;
    asm("cvt.rn.satfinite.bf16x2.f32 %0, %1, %2;" : "=r"(r) : "f"(v.y), "f"(v.x));
    return r;
}
__device__ __forceinline__ void splitf2(float2 v, uint32_t& h, uint32_t& l) {
    h = packb(v);
    float hx = __uint_as_float(h << 16);
    float hy = __uint_as_float(h & 0xFFFF0000u);
    l = packb(make_float2(v.x - hx, v.y - hy));
}
__device__ __forceinline__ void mma16816(float c[4],
    const uint32_t a[4], uint32_t b0, uint32_t b1)
{
    asm volatile(
        "mma.sync.aligned.m16n8k16.row.col.f32.bf16.bf16.f32 "
        "{%0,%1,%2,%3},{%4,%5,%6,%7},{%8,%9},{%0,%1,%2,%3};"
        : "+f"(c[0]), "+f"(c[1]), "+f"(c[2]), "+f"(c[3])
        : "r"(a[0]), "r"(a[1]), "r"(a[2]), "r"(a[3]), "r"(b0), "r"(b1));
}
#define PAIR_BAR(mol) asm volatile("bar.sync %0, 64;" :: "r"(1 + (mol)) : "memory")

// 9 n-tiles, one k16 step, TWO m-tiles sharing each B-fragment load.
template<int TERMS>
__device__ __forceinline__ void mma_n9x2(
    const uint32_t* __restrict__ Bhi, const uint32_t* __restrict__ Blo,
    int rbase, int sb, int q,
    const uint32_t ah0[4], const uint32_t al0[4],
    const uint32_t ah1[4], const uint32_t al1[4],
    float C0[9][4], float C1[9][4])
{
    #pragma unroll
    for (int n = 0; n < 9; n++) {
        const int rb = (n * 8 + q) * sb + rbase;
        uint32_t bh0 = Bhi[rb], bh1 = Bhi[rb + 4];
        mma16816(C0[n], ah0, bh0, bh1);
        mma16816(C1[n], ah1, bh0, bh1);
        if (TERMS >= 2) {
            uint32_t bl0 = Blo[rb], bl1 = Blo[rb + 4];
            mma16816(C0[n], ah0, bl0, bl1);
            mma16816(C1[n], ah1, bl0, bl1);
        }
        if (TERMS == 3) {
            mma16816(C0[n], al0, bh0, bh1);
            mma16816(C1[n], al1, bh0, bh1);
        }
    }
}

// ---------------- merged prep: W split tiles + embed split ----------------
__global__ void prep_all(const float* __restrict__ w1, const float* __restrict__ w2,
                         const float* __restrict__ emb) {
    const int idx = blockIdx.x * 256 + threadIdx.x;
    if (idx < 2 * 72 * 88) {
        int l = idx / (72 * 88);
        int r = idx % (72 * 88);
        int n = r / 88, k = r % 88;
        const float* w = l ? w2 : w1;
        float v = (n < 70 && k < 70) ? w[k * 70 + n] : 0.f;
        uint16_t h, lo; split2(v, h, lo);
        *(uint16_t*)(g_wt[l][0] + r * 2) = h;
        *(uint16_t*)(g_wt[l][1] + r * 2) = lo;
    }
    const int eidx = idx - 2 * 72 * 88;
    if (eidx >= 0 && eidx < 10000 * 40) {
        int a = eidx / 40, w = eidx % 40;
        uint32_t hw = 0, lw = 0;
        if (w < 35) {
            const float2 v = *(const float2*)(emb + (size_t)a * 70 + 2 * w);
            splitf2(v, hw, lw);
        }
        g_emb[a][2 * w]     = hw;
        g_emb[a][2 * w + 1] = lw;
    }
}

// ---------------- main kernel ----------------
__global__ __launch_bounds__(128, 3)
void pathway_mmaA(const int* __restrict__ atoms, const float* __restrict__ adj,
                  const float* __restrict__ sel,
                  const float* __restrict__ b1, const float* __restrict__ b2,
                  const float* __restrict__ wp, const float* __restrict__ bp,
                  float* __restrict__ out)
{
    extern __shared__ __align__(16) unsigned char sm[];
    float* smf = (float*)sm;
    const int t = threadIdx.x, lane = t & 31, wid = t >> 5;
    const int bid = blockIdx.x;
    const int q = lane >> 2, qp = lane & 3;
    const int mol = wid >> 1;                 // molecule 0/1
    const int mrow = wid * 32;                // warp's global row base
    const int mloc = mrow & 63;               // 0 or 32 within molecule

    uint32_t* W1hi = (uint32_t*)(sm + OFF_W1);  uint32_t* W1lo = W1hi + 72 * SWW;
    uint32_t* W2hi = (uint32_t*)(sm + OFF_W2);  uint32_t* W2lo = W2hi + 72 * SWW;
    uint32_t* Hhi = (uint32_t*)(sm + OFF_H + mol * HTILE);
    uint16_t* H16h = (uint16_t*)(sm + OFF_H + mol * HTILE);

    // ===== phase 0: colsum partials + W1 + W2 + consts =====
    {
        const float2* Ab = (const float2*)(adj + (size_t)bid * 8192);
        float2 cs0 = make_float2(0.f, 0.f), cs1 = make_float2(0.f, 0.f);
        #pragma unroll
        for (int k = 0; k < 32; k++) {
            float2 v = __ldg(&Ab[t + 128 * k]);
            if (k < 16) { cs0.x += v.x; cs0.y += v.y; }
            else        { cs1.x += v.x; cs1.y += v.y; }
        }
        const int g = t >> 5, c0 = (t & 31) * 2;
        smf[CSP + g * 128 + c0]          = cs0.x;
        smf[CSP + g * 128 + c0 + 1]      = cs0.y;
        smf[CSP + g * 128 + 64 + c0]     = cs1.x;
        smf[CSP + g * 128 + 64 + c0 + 1] = cs1.y;
    }
    {   // W1 + W2 split tiles (separate regions)
        const uint4* gw1 = (const uint4*)g_wt[0][0];
        const uint4* gw2 = (const uint4*)g_wt[1][0];
        uint4* sw1 = (uint4*)(sm + OFF_W1);
        uint4* sw2 = (uint4*)(sm + OFF_W2);
        #pragma unroll
        for (int i = t; i < 2 * WTILE / 16; i += 128) {
            sw1[i] = gw1[i];
            sw2[i] = gw2[i];
        }
    }
    if (t < 72) { smf[B1I + t] = (t < 70) ? b1[t] : 0.f;
                  smf[B2I + t] = (t < 70) ? b2[t] : 0.f; }
    if (t < 11) smf[BPI + t] = bp[t];
    __syncthreads();   // the ONLY CTA-wide barrier

    // colsum reduce -> CSI (read later by own pair only after pair bars)
    smf[CSI + t] = smf[CSP + t] + smf[CSP + 128 + t]
                 + smf[CSP + 256 + t] + smf[CSP + 384 + t];

    float C0[9][4], C1[9][4];
    #pragma unroll
    for (int n = 0; n < 9; n++)
        #pragma unroll
        for (int i = 0; i < 4; i++) { C0[n][i] = 0.f; C1[n][i] = 0.f; }

    // ====== GEMM1: D1 = X @ W1^T (K=80, 3-term, pre-split LDG.64 frags) ====
    {
        const int abase = bid * 128 + mrow + q;
        const uint32_t* e00 = g_emb[__ldg(&atoms[abase])];
        const uint32_t* e01 = g_emb[__ldg(&atoms[abase + 8])];
        const uint32_t* e10 = g_emb[__ldg(&atoms[abase + 16])];
        const uint32_t* e11 = g_emb[__ldg(&atoms[abase + 24])];

        uint2 va[8], vb[8];
        {
            const int w0 = 2 * qp, w1 = w0 + 8;
            va[0] = __ldg((const uint2*)(e00 + w0));
            va[1] = __ldg((const uint2*)(e01 + w0));
            va[2] = __ldg((const uint2*)(e00 + w1));
            va[3] = __ldg((const uint2*)(e01 + w1));
            va[4] = __ldg((const uint2*)(e10 + w0));
            va[5] = __ldg((const uint2*)(e11 + w0));
            va[6] = __ldg((const uint2*)(e10 + w1));
            va[7] = __ldg((const uint2*)(e11 + w1));
        }
        #pragma unroll
        for (int ks = 0; ks < 5; ks++) {
            uint2* cur = (ks & 1) ? vb : va;
            uint2* nxt = (ks & 1) ? va : vb;
            if (ks < 4) {
                const int w0 = 16 * (ks + 1) + 2 * qp, w1 = w0 + 8;
                nxt[0] = __ldg((const uint2*)(e00 + w0));
                nxt[1] = __ldg((const uint2*)(e01 + w0));
                nxt[2] = __ldg((const uint2*)(e00 + w1));
                nxt[3] = __ldg((const uint2*)(e01 + w1));
                nxt[4] = __ldg((const uint2*)(e10 + w0));
                nxt[5] = __ldg((const uint2*)(e11 + w0));
                nxt[6] = __ldg((const uint2*)(e10 + w1));
                nxt[7] = __ldg((const uint2*)(e11 + w1));
            }
            uint32_t ah0[4] = {cur[0].x, cur[1].x, cur[2].x, cur[3].x};
            uint32_t al0[4] = {cur[0].y, cur[1].y, cur[2].y, cur[3].y};
            uint32_t ah1[4] = {cur[4].x, cur[5].x, cur[6].x, cur[7].x};
            uint32_t al1[4] = {cur[4].y, cur[5].y, cur[6].y, cur[7].y};
            mma_n9x2<3>(W1hi, W1lo, ks * 8 + qp, SWW, q,
                        ah0, al0, ah1, al1, C0, C1);
        }
    }

    // ---- epi1: H1 = relu(D1+b1) -> H^T (hi only, per-mol region) ----
    #pragma unroll
    for (int m2 = 0; m2 < 2; m2++) {
        float (*C)[4] = m2 ? C1 : C0;
        const int r0 = mloc + m2 * 16 + q, r1 = r0 + 8;
        #pragma unroll
        for (int n = 0; n < 9; n++) {
            const int d0 = n * 8 + qp * 2;
            H16h[d0 * 72 + r0]       = bf16h(fmaxf(C[n][0] + smf[B1I + d0], 0.f));
            H16h[(d0 + 1) * 72 + r0] = bf16h(fmaxf(C[n][1] + smf[B1I + d0 + 1], 0.f));
            H16h[d0 * 72 + r1]       = bf16h(fmaxf(C[n][2] + smf[B1I + d0], 0.f));
            H16h[(d0 + 1) * 72 + r1] = bf16h(fmaxf(C[n][3] + smf[B1I + d0 + 1], 0.f));
        }
    }
    PAIR_BAR(mol);     // H of this molecule complete (written by this warp pair)

    // ====== GEMM2: D2 = A @ H1 (K=64, 1-term bf16, JIT A-frags) ============
    #pragma unroll
    for (int n = 0; n < 9; n++)
        #pragma unroll
        for (int i = 0; i < 4; i++) { C0[n][i] = 0.f; C1[n][i] = 0.f; }
    {
        const float2* A2 = (const float2*)(adj + ((size_t)(2 * bid) + mol) * 4096);
        const int rb = (mloc + q) * 32;
        float2 va[8], vb[8];
        {
            const int cp0 = qp, cp1 = qp + 4;
            va[0] = __ldg(&A2[rb + cp0]);       va[1] = __ldg(&A2[rb + 256 + cp0]);
            va[2] = __ldg(&A2[rb + cp1]);       va[3] = __ldg(&A2[rb + 256 + cp1]);
            va[4] = __ldg(&A2[rb + 512 + cp0]); va[5] = __ldg(&A2[rb + 768 + cp0]);
            va[6] = __ldg(&A2[rb + 512 + cp1]); va[7] = __ldg(&A2[rb + 768 + cp1]);
        }
        #pragma unroll
        for (int ks = 0; ks < 4; ks++) {
            float2* cur = (ks & 1) ? vb : va;
            float2* nxt = (ks & 1) ? va : vb;
            if (ks < 3) {
                const int cp0 = 8 * (ks + 1) + qp, cp1 = cp0 + 4;
                nxt[0] = __ldg(&A2[rb + cp0]);       nxt[1] = __ldg(&A2[rb + 256 + cp0]);
                nxt[2] = __ldg(&A2[rb + cp1]);       nxt[3] = __ldg(&A2[rb + 256 + cp1]);
                nxt[4] = __ldg(&A2[rb + 512 + cp0]); nxt[5] = __ldg(&A2[rb + 768 + cp0]);
                nxt[6] = __ldg(&A2[rb + 512 + cp1]); nxt[7] = __ldg(&A2[rb + 768 + cp1]);
            }
            uint32_t a0[4], a1[4];
            a0[0] = packb(cur[0]); a0[1] = packb(cur[1]);
            a0[2] = packb(cur[2]); a0[3] = packb(cur[3]);
            a1[0] = packb(cur[4]); a1[1] = packb(cur[5]);
            a1[2] = packb(cur[6]); a1[3] = packb(cur[7]);
            mma_n9x2<1>(Hhi, Hhi, ks * 8 + qp, SHW, q, a0, a0, a1, a1, C0, C1);
        }
    }
    // no barrier: W2 was preloaded in phase 0, D2 lives in registers

    // ================= GEMM3: D3 = D2 @ W2^T (chained, K=80, 3-term) =======
    float C3a[9][4], C3b[9][4];
    #pragma unroll
    for (int n = 0; n < 9; n++)
        #pragma unroll
        for (int i = 0; i < 4; i++) { C3a[n][i] = 0.f; C3b[n][i] = 0.f; }
    #pragma unroll
    for (int ks = 0; ks < 5; ks++) {
        uint32_t ah0[4], al0[4], ah1[4], al1[4];
        splitf2(make_float2(C0[2*ks][0], C0[2*ks][1]), ah0[0], al0[0]);
        splitf2(make_float2(C0[2*ks][2], C0[2*ks][3]), ah0[1], al0[1]);
        splitf2(make_float2(C1[2*ks][0], C1[2*ks][1]), ah1[0], al1[0]);
        splitf2(make_float2(C1[2*ks][2], C1[2*ks][3]), ah1[1], al1[1]);
        if (ks < 4) {
            splitf2(make_float2(C0[2*ks+1][0], C0[2*ks+1][1]), ah0[2], al0[2]);
            splitf2(make_float2(C0[2*ks+1][2], C0[2*ks+1][3]), ah0[3], al0[3]);
            splitf2(make_float2(C1[2*ks+1][0], C1[2*ks+1][1]), ah1[2], al1[2]);
            splitf2(make_float2(C1[2*ks+1][2], C1[2*ks+1][3]), ah1[3], al1[3]);
        } else {
            ah0[2] = al0[2] = ah0[3] = al0[3] = 0u;
            ah1[2] = al1[2] = ah1[3] = al1[3] = 0u;
        }
        mma_n9x2<3>(W2hi, W2lo, ks * 8 + qp, SWW, q,
                    ah0, al0, ah1, al1, C3a, C3b);
    }

    // ---- epi3: pool partials y[d] += csum[r] * relu(D3[r][d]+b2[d]) ----
    {
        const float cs00 = smf[CSI + mrow + q];
        const float cs01 = smf[CSI + mrow + q + 8];
        const float cs10 = smf[CSI + mrow + q + 16];
        const float cs11 = smf[CSI + mrow + q + 24];
        #pragma unroll
        for (int n = 0; n < 9; n++) {
            #pragma unroll
            for (int j = 0; j < 2; j++) {
                const int d = n * 8 + qp * 2 + j;
                const float bb = smf[B2I + d];
                float v = cs00 * fmaxf(C3a[n][j] + bb, 0.f)
                        + cs01 * fmaxf(C3a[n][2 + j] + bb, 0.f)
                        + cs10 * fmaxf(C3b[n][j] + bb, 0.f)
                        + cs11 * fmaxf(C3b[n][2 + j] + bb, 0.f);
                v += __shfl_xor_sync(0xFFFFFFFFu, v, 4);
                v += __shfl_xor_sync(0xFFFFFFFFu, v, 8);
                v += __shfl_xor_sync(0xFFFFFFFFu, v, 16);
                if (q == 0) smf[PLI + wid * 72 + d] = v;
            }
        }
    }
    PAIR_BAR(mol);     // pool partials of this molecule complete

    // ---- pair-leader warp: reduce 2 warps -> y, then head (per molecule) ---
    if ((wid & 1) == 0) {
        for (int i = lane; i < 72; i += 32)
            smf[YI + mol * 72 + i] = smf[PLI + (mol * 2 + 0) * 72 + i]
                                   + smf[PLI + (mol * 2 + 1) * 72 + i];
        __syncwarp();
        if (lane < 11) {
            const int c = lane;
            float s = smf[BPI + c];
            #pragma unroll 7
            for (int d = 0; d < 70; d++)
                s += smf[YI + mol * 72 + d] * __ldg(&wp[d * 11 + c]);
            const float* sv = sel + (size_t)(2 * bid + mol) * 7;
            #pragma unroll
            for (int e = 0; e < 7; e++)
                s += __ldg(&sv[e]) * __ldg(&wp[(70 + e) * 11 + c]);
            out[(size_t)(2 * bid + mol) * 11 + c] = s;
        }
    }
}

extern "C" void kernel_launch(void* const* d_in, const int* in_sizes, int n_in,
                              void* d_out, int out_size)
{
    const int*   atoms = (const int*)  d_in[0];
    const float* adj   = (const float*)d_in[1];
    const float* sel   = (const float*)d_in[2];
    const float* emb   = (const float*)d_in[3];
    const float* w1    = (const float*)d_in[4];
    const float* b1    = (const float*)d_in[5];
    const float* w2    = (const float*)d_in[6];
    const float* b2    = (const float*)d_in[7];
    const float* wp    = (const float*)d_in[8];
    const float* bp    = (const float*)d_in[9];
    float* out = (float*)d_out;

    const int prep_items = 2 * 72 * 88 + 10000 * 40;
    prep_all<<<(prep_items + 255) / 256, 256>>>(w1, w2, emb);

    cudaFuncSetAttribute(pathway_mmaA,
                         cudaFuncAttributeMaxDynamicSharedMemorySize, SMEM_BYTES);
    pathway_mmaA<<<4096, 128, SMEM_BYTES>>>(atoms, adj, sel,
                                            b1, b2, wp, bp, out);
}

// round 17
// speedup vs baseline: 1.1139x; 1.1139x over previous
#include <cuda_runtime.h>
#include <cuda_bf16.h>
#include <cstdint>

// ============================================================================
// PathwayPredictor, mma.sync bf16-split, 2 molecules/CTA, 128 threads,
// M=32 per warp, 3 CTAs/SM (smem 49.5KB).
// GEMM1: X(pre-split embed table, LDG.64 frags) @ W1^T [K=80, 3-term]
// GEMM2: A(JIT gmem frags, L2-prefetched) @ H1(smem, hi) [K=64, 1-term bf16]
//        colsum(A) accumulated FROM the same fragments (no second A read).
// GEMM3: D2 (in-register chain) @ W2^T [K=80, 3-term]; W2 loaded after epi1
//        (overlaps GEMM2 -- load-bearing overlap, do not move).
// pool collapse: y = colsum(A) @ relu(D3+b2); tiny head.
// Single merged prep kernel (W split + embed split).
// ============================================================================

#define SWW 44   // W row stride, u32 words (88 bf16)
#define SHW 36   // H row stride, u32 words (72 bf16)

// smem float indices
#define B1I 0       // b1 padded [72]
#define B2I 72      // b2 padded [72]
#define BPI 144     // bp [16]
#define CSP 160     // colsum partials [4 warps][64 cols] (written post-GEMM2)
#define PLI 416     // pool partials [4][72]
#define YI  704     // y [2][72]  (ends 848)
// byte offsets
#define OFF_H 3456      // 2 x (72x72 hi) b16 = 20736
#define OFF_W 24192     // 72x88 hi + lo = 25344 (W1 then W2)
#define SMEM_BYTES 49536
#define WTILE 12672
#define HTILE 10368

__device__ __align__(16) unsigned char g_wt[2][2][WTILE];   // [layer][hi/lo]
__device__ __align__(16) uint32_t g_emb[10000][80];         // {hi,lo} word pairs

// ---------------- helpers ----------------
__device__ __forceinline__ uint16_t bf16h(float v) {
    __nv_bfloat16 b = __float2bfloat16(v);
    return *reinterpret_cast<uint16_t*>(&b);
}
__device__ __forceinline__ void split2(float v, uint16_t& h, uint16_t& l) {
    __nv_bfloat16 bh = __float2bfloat16(v);
    h = *reinterpret_cast<uint16_t*>(&bh);
    __nv_bfloat16 bl = __float2bfloat16(v - __bfloat162float(bh));
    l = *reinterpret_cast<uint16_t*>(&bl);
}
__device__ __forceinline__ uint32_t packb(float2 v) {   // lo16=bf16(v.x), hi16=bf16(v.y)
    uint32_t r;
    asm("cvt.rn.satfinite.bf16x2.f32 %0, %1, %2;" : "=r"(r) : "f"(v.y), "f"(v.x));
    return r;
}
__device__ __forceinline__ void splitf2(float2 v, uint32_t& h, uint32_t& l) {
    h = packb(v);
    float hx = __uint_as_float(h << 16);
    float hy = __uint_as_float(h & 0xFFFF0000u);
    l = packb(make_float2(v.x - hx, v.y - hy));
}
__device__ __forceinline__ void mma16816(float c[4],
    const uint32_t a[4], uint32_t b0, uint32_t b1)
{
    asm volatile(
        "mma.sync.aligned.m16n8k16.row.col.f32.bf16.bf16.f32 "
        "{%0,%1,%2,%3},{%4,%5,%6,%7},{%8,%9},{%0,%1,%2,%3};"
        : "+f"(c[0]), "+f"(c[1]), "+f"(c[2]), "+f"(c[3])
        : "r"(a[0]), "r"(a[1]), "r"(a[2]), "r"(a[3]), "r"(b0), "r"(b1));
}

// 9 n-tiles, one k16 step, TWO m-tiles sharing each B-fragment load.
template<int TERMS>
__device__ __forceinline__ void mma_n9x2(
    const uint32_t* __restrict__ Bhi, const uint32_t* __restrict__ Blo,
    int rbase, int sb, int q,
    const uint32_t ah0[4], const uint32_t al0[4],
    const uint32_t ah1[4], const uint32_t al1[4],
    float C0[9][4], float C1[9][4])
{
    #pragma unroll
    for (int n = 0; n < 9; n++) {
        const int rb = (n * 8 + q) * sb + rbase;
        uint32_t bh0 = Bhi[rb], bh1 = Bhi[rb + 4];
        mma16816(C0[n], ah0, bh0, bh1);
        mma16816(C1[n], ah1, bh0, bh1);
        if (TERMS >= 2) {
            uint32_t bl0 = Blo[rb], bl1 = Blo[rb + 4];
            mma16816(C0[n], ah0, bl0, bl1);
            mma16816(C1[n], ah1, bl0, bl1);
        }
        if (TERMS == 3) {
            mma16816(C0[n], al0, bh0, bh1);
            mma16816(C1[n], al1, bh0, bh1);
        }
    }
}

// ---------------- merged prep: W split tiles + embed split ----------------
__global__ void prep_all(const float* __restrict__ w1, const float* __restrict__ w2,
                         const float* __restrict__ emb) {
    const int idx = blockIdx.x * 256 + threadIdx.x;
    if (idx < 2 * 72 * 88) {
        int l = idx / (72 * 88);
        int r = idx % (72 * 88);
        int n = r / 88, k = r % 88;
        const float* w = l ? w2 : w1;
        float v = (n < 70 && k < 70) ? w[k * 70 + n] : 0.f;
        uint16_t h, lo; split2(v, h, lo);
        *(uint16_t*)(g_wt[l][0] + r * 2) = h;
        *(uint16_t*)(g_wt[l][1] + r * 2) = lo;
    }
    const int eidx = idx - 2 * 72 * 88;
    if (eidx >= 0 && eidx < 10000 * 40) {
        int a = eidx / 40, w = eidx % 40;
        uint32_t hw = 0, lw = 0;
        if (w < 35) {
            const float2 v = *(const float2*)(emb + (size_t)a * 70 + 2 * w);
            splitf2(v, hw, lw);
        }
        g_emb[a][2 * w]     = hw;
        g_emb[a][2 * w + 1] = lw;
    }
}

// ---------------- main kernel ----------------
__global__ __launch_bounds__(128, 3)
void pathway_mmaB(const int* __restrict__ atoms, const float* __restrict__ adj,
                  const float* __restrict__ sel,
                  const float* __restrict__ b1, const float* __restrict__ b2,
                  const float* __restrict__ wp, const float* __restrict__ bp,
                  float* __restrict__ out)
{
    extern __shared__ __align__(16) unsigned char sm[];
    float* smf = (float*)sm;
    const int t = threadIdx.x, lane = t & 31, wid = t >> 5;
    const int bid = blockIdx.x;
    const int q = lane >> 2, qp = lane & 3;
    const int mol = wid >> 1;                 // molecule 0/1
    const int mrow = wid * 32;                // warp's global row base
    const int mloc = mrow & 63;               // 0 or 32 within molecule

    uint32_t* Whi = (uint32_t*)(sm + OFF_W);  uint32_t* Wlo = Whi + 72 * SWW;
    uint32_t* Hhi = (uint32_t*)(sm + OFF_H + mol * HTILE);
    uint16_t* H16h = (uint16_t*)(sm + OFF_H + mol * HTILE);

    // ===== phase 0: W1 tiles + consts + L2 prefetch of A (no A data pass) ==
    {
        const float* Ap = adj + (size_t)bid * 8192;
        asm volatile("prefetch.global.L2 [%0];" :: "l"(Ap + t * 32));
        asm volatile("prefetch.global.L2 [%0];" :: "l"(Ap + 4096 + t * 32));
    }
    {   // W1 split tiles
        const uint4* gw = (const uint4*)g_wt[0][0];
        uint4* sw = (uint4*)(sm + OFF_W);
        #pragma unroll
        for (int i = t; i < 2 * WTILE / 16; i += 128) sw[i] = gw[i];
    }
    if (t < 72) { smf[B1I + t] = (t < 70) ? b1[t] : 0.f;
                  smf[B2I + t] = (t < 70) ? b2[t] : 0.f; }
    if (t < 11) smf[BPI + t] = bp[t];
    __syncthreads();

    float C0[9][4], C1[9][4];
    #pragma unroll
    for (int n = 0; n < 9; n++)
        #pragma unroll
        for (int i = 0; i < 4; i++) { C0[n][i] = 0.f; C1[n][i] = 0.f; }

    // ====== GEMM1: D1 = X @ W1^T (K=80, 3-term, pre-split LDG.64 frags) ====
    {
        const int abase = bid * 128 + mrow + q;
        const uint32_t* e00 = g_emb[__ldg(&atoms[abase])];
        const uint32_t* e01 = g_emb[__ldg(&atoms[abase + 8])];
        const uint32_t* e10 = g_emb[__ldg(&atoms[abase + 16])];
        const uint32_t* e11 = g_emb[__ldg(&atoms[abase + 24])];

        uint2 va[8], vb[8];
        {
            const int w0 = 2 * qp, w1 = w0 + 8;
            va[0] = __ldg((const uint2*)(e00 + w0));
            va[1] = __ldg((const uint2*)(e01 + w0));
            va[2] = __ldg((const uint2*)(e00 + w1));
            va[3] = __ldg((const uint2*)(e01 + w1));
            va[4] = __ldg((const uint2*)(e10 + w0));
            va[5] = __ldg((const uint2*)(e11 + w0));
            va[6] = __ldg((const uint2*)(e10 + w1));
            va[7] = __ldg((const uint2*)(e11 + w1));
        }
        #pragma unroll
        for (int ks = 0; ks < 5; ks++) {
            uint2* cur = (ks & 1) ? vb : va;
            uint2* nxt = (ks & 1) ? va : vb;
            if (ks < 4) {
                const int w0 = 16 * (ks + 1) + 2 * qp, w1 = w0 + 8;
                nxt[0] = __ldg((const uint2*)(e00 + w0));
                nxt[1] = __ldg((const uint2*)(e01 + w0));
                nxt[2] = __ldg((const uint2*)(e00 + w1));
                nxt[3] = __ldg((const uint2*)(e01 + w1));
                nxt[4] = __ldg((const uint2*)(e10 + w0));
                nxt[5] = __ldg((const uint2*)(e11 + w0));
                nxt[6] = __ldg((const uint2*)(e10 + w1));
                nxt[7] = __ldg((const uint2*)(e11 + w1));
            }
            uint32_t ah0[4] = {cur[0].x, cur[1].x, cur[2].x, cur[3].x};
            uint32_t al0[4] = {cur[0].y, cur[1].y, cur[2].y, cur[3].y};
            uint32_t ah1[4] = {cur[4].x, cur[5].x, cur[6].x, cur[7].x};
            uint32_t al1[4] = {cur[4].y, cur[5].y, cur[6].y, cur[7].y};
            mma_n9x2<3>(Whi, Wlo, ks * 8 + qp, SWW, q,
                        ah0, al0, ah1, al1, C0, C1);
        }
    }

    // ---- epi1: H1 = relu(D1+b1) -> H^T (hi only, per-mol region) ----
    #pragma unroll
    for (int m2 = 0; m2 < 2; m2++) {
        float (*C)[4] = m2 ? C1 : C0;
        const int r0 = mloc + m2 * 16 + q, r1 = r0 + 8;
        #pragma unroll
        for (int n = 0; n < 9; n++) {
            const int d0 = n * 8 + qp * 2;
            H16h[d0 * 72 + r0]       = bf16h(fmaxf(C[n][0] + smf[B1I + d0], 0.f));
            H16h[(d0 + 1) * 72 + r0] = bf16h(fmaxf(C[n][1] + smf[B1I + d0 + 1], 0.f));
            H16h[d0 * 72 + r1]       = bf16h(fmaxf(C[n][2] + smf[B1I + d0], 0.f));
            H16h[(d0 + 1) * 72 + r1] = bf16h(fmaxf(C[n][3] + smf[B1I + d0 + 1], 0.f));
        }
    }
    __syncthreads();   // H ready; W1 consumed

    {   // W2 split tiles over W1 (overlaps GEMM2; completes before next sync)
        const uint4* gw = (const uint4*)g_wt[1][0];
        uint4* sw = (uint4*)(sm + OFF_W);
        #pragma unroll
        for (int i = t; i < 2 * WTILE / 16; i += 128) sw[i] = gw[i];
    }

    // ====== GEMM2: D2 = A @ H1 (K=64, 1-term bf16) + colsum from frags =====
    #pragma unroll
    for (int n = 0; n < 9; n++)
        #pragma unroll
        for (int i = 0; i < 4; i++) { C0[n][i] = 0.f; C1[n][i] = 0.f; }
    float2 csa[4][2];     // per-ks column-sum partials over this thread's 4 rows
    {
        const float2* A2 = (const float2*)(adj + ((size_t)(2 * bid) + mol) * 4096);
        const int rb = (mloc + q) * 32;
        float2 va[8], vb[8];
        {
            const int cp0 = qp, cp1 = qp + 4;
            va[0] = __ldg(&A2[rb + cp0]);       va[1] = __ldg(&A2[rb + 256 + cp0]);
            va[2] = __ldg(&A2[rb + cp1]);       va[3] = __ldg(&A2[rb + 256 + cp1]);
            va[4] = __ldg(&A2[rb + 512 + cp0]); va[5] = __ldg(&A2[rb + 768 + cp0]);
            va[6] = __ldg(&A2[rb + 512 + cp1]); va[7] = __ldg(&A2[rb + 768 + cp1]);
        }
        #pragma unroll
        for (int ks = 0; ks < 4; ks++) {
            float2* cur = (ks & 1) ? vb : va;
            float2* nxt = (ks & 1) ? va : vb;
            if (ks < 3) {
                const int cp0 = 8 * (ks + 1) + qp, cp1 = cp0 + 4;
                nxt[0] = __ldg(&A2[rb + cp0]);       nxt[1] = __ldg(&A2[rb + 256 + cp0]);
                nxt[2] = __ldg(&A2[rb + cp1]);       nxt[3] = __ldg(&A2[rb + 256 + cp1]);
                nxt[4] = __ldg(&A2[rb + 512 + cp0]); nxt[5] = __ldg(&A2[rb + 768 + cp0]);
                nxt[6] = __ldg(&A2[rb + 512 + cp1]); nxt[7] = __ldg(&A2[rb + 768 + cp1]);
            }
            csa[ks][0].x = cur[0].x + cur[1].x + cur[4].x + cur[5].x;
            csa[ks][0].y = cur[0].y + cur[1].y + cur[4].y + cur[5].y;
            csa[ks][1].x = cur[2].x + cur[3].x + cur[6].x + cur[7].x;
            csa[ks][1].y = cur[2].y + cur[3].y + cur[6].y + cur[7].y;
            uint32_t a0[4], a1[4];
            a0[0] = packb(cur[0]); a0[1] = packb(cur[1]);
            a0[2] = packb(cur[2]); a0[3] = packb(cur[3]);
            a1[0] = packb(cur[4]); a1[1] = packb(cur[5]);
            a1[2] = packb(cur[6]); a1[3] = packb(cur[7]);
            mma_n9x2<1>(Hhi, Hhi, ks * 8 + qp, SHW, q, a0, a0, a1, a1, C0, C1);
        }
    }
    // shfl-reduce colsum partials over q; lanes 0..3 write warp partials [64]
    #pragma unroll
    for (int ks = 0; ks < 4; ks++)
        #pragma unroll
        for (int j = 0; j < 2; j++) {
            float x = csa[ks][j].x, y = csa[ks][j].y;
            x += __shfl_xor_sync(0xFFFFFFFFu, x, 4);
            y += __shfl_xor_sync(0xFFFFFFFFu, y, 4);
            x += __shfl_xor_sync(0xFFFFFFFFu, x, 8);
            y += __shfl_xor_sync(0xFFFFFFFFu, y, 8);
            x += __shfl_xor_sync(0xFFFFFFFFu, x, 16);
            y += __shfl_xor_sync(0xFFFFFFFFu, y, 16);
            if (lane < 4) {
                smf[CSP + wid * 64 + 16 * ks + 8 * j + 2 * qp]     = x;
                smf[CSP + wid * 64 + 16 * ks + 8 * j + 2 * qp + 1] = y;
            }
        }
    __syncthreads();   // W2 stores + CSP partials complete

    // ================= GEMM3: D3 = D2 @ W2^T (chained, K=80, 3-term) =======
    float C3a[9][4], C3b[9][4];
    #pragma unroll
    for (int n = 0; n < 9; n++)
        #pragma unroll
        for (int i = 0; i < 4; i++) { C3a[n][i] = 0.f; C3b[n][i] = 0.f; }
    #pragma unroll
    for (int ks = 0; ks < 5; ks++) {
        uint32_t ah0[4], al0[4], ah1[4], al1[4];
        splitf2(make_float2(C0[2*ks][0], C0[2*ks][1]), ah0[0], al0[0]);
        splitf2(make_float2(C0[2*ks][2], C0[2*ks][3]), ah0[1], al0[1]);
        splitf2(make_float2(C1[2*ks][0], C1[2*ks][1]), ah1[0], al1[0]);
        splitf2(make_float2(C1[2*ks][2], C1[2*ks][3]), ah1[1], al1[1]);
        if (ks < 4) {
            splitf2(make_float2(C0[2*ks+1][0], C0[2*ks+1][1]), ah0[2], al0[2]);
            splitf2(make_float2(C0[2*ks+1][2], C0[2*ks+1][3]), ah0[3], al0[3]);
            splitf2(make_float2(C1[2*ks+1][0], C1[2*ks+1][1]), ah1[2], al1[2]);
            splitf2(make_float2(C1[2*ks+1][2], C1[2*ks+1][3]), ah1[3], al1[3]);
        } else {
            ah0[2] = al0[2] = ah0[3] = al0[3] = 0u;
            ah1[2] = al1[2] = ah1[3] = al1[3] = 0u;
        }
        mma_n9x2<3>(Whi, Wlo, ks * 8 + qp, SWW, q,
                    ah0, al0, ah1, al1, C3a, C3b);
    }

    // ---- epi3: pool partials y[d] += csum[r] * relu(D3[r][d]+b2[d]) ----
    {
        const int p0 = (mol * 2) * 64 + mloc + q;      // pair warp partials
        const int p1 = p0 + 64;
        const float cs00 = smf[CSP + p0]      + smf[CSP + p1];
        const float cs01 = smf[CSP + p0 + 8]  + smf[CSP + p1 + 8];
        const float cs10 = smf[CSP + p0 + 16] + smf[CSP + p1 + 16];
        const float cs11 = smf[CSP + p0 + 24] + smf[CSP + p1 + 24];
        #pragma unroll
        for (int n = 0; n < 9; n++) {
            #pragma unroll
            for (int j = 0; j < 2; j++) {
                const int d = n * 8 + qp * 2 + j;
                const float bb = smf[B2I + d];
                float v = cs00 * fmaxf(C3a[n][j] + bb, 0.f)
                        + cs01 * fmaxf(C3a[n][2 + j] + bb, 0.f)
                        + cs10 * fmaxf(C3b[n][j] + bb, 0.f)
                        + cs11 * fmaxf(C3b[n][2 + j] + bb, 0.f);
                v += __shfl_xor_sync(0xFFFFFFFFu, v, 4);
                v += __shfl_xor_sync(0xFFFFFFFFu, v, 8);
                v += __shfl_xor_sync(0xFFFFFFFFu, v, 16);
                if (q == 0) smf[PLI + wid * 72 + d] = v;
            }
        }
    }
    __syncthreads();

    // reduce 2 warps per molecule (144 entries, strided over 128 threads)
    for (int i = t; i < 144; i += 128) {
        const int mY = i / 72, d = i - mY * 72;
        smf[YI + i] = smf[PLI + (mY * 2 + 0) * 72 + d]
                    + smf[PLI + (mY * 2 + 1) * 72 + d];
    }
    __syncthreads();

    // head
    if (t < 22) {
        const int mH = t / 11, c = t - mH * 11;
        float s = smf[BPI + c];
        #pragma unroll 7
        for (int d = 0; d < 70; d++)
            s += smf[YI + mH * 72 + d] * __ldg(&wp[d * 11 + c]);
        const float* sv = sel + (size_t)(2 * bid + mH) * 7;
        #pragma unroll
        for (int e = 0; e < 7; e++)
            s += __ldg(&sv[e]) * __ldg(&wp[(70 + e) * 11 + c]);
        out[(size_t)(2 * bid + mH) * 11 + c] = s;
    }
}

extern "C" void kernel_launch(void* const* d_in, const int* in_sizes, int n_in,
                              void* d_out, int out_size)
{
    const int*   atoms = (const int*)  d_in[0];
    const float* adj   = (const float*)d_in[1];
    const float* sel   = (const float*)d_in[2];
    const float* emb   = (const float*)d_in[3];
    const float* w1    = (const float*)d_in[4];
    const float* b1    = (const float*)d_in[5];
    const float* w2    = (const float*)d_in[6];
    const float* b2    = (const float*)d_in[7];
    const float* wp    = (const float*)d_in[8];
    const float* bp    = (const float*)d_in[9];
    float* out = (float*)d_out;

    const int prep_items = 2 * 72 * 88 + 10000 * 40;
    prep_all<<<(prep_items + 255) / 256, 256>>>(w1, w2, emb);

    cudaFuncSetAttribute(pathway_mmaB,
                         cudaFuncAttributeMaxDynamicSharedMemorySize, SMEM_BYTES);
    pathway_mmaB<<<4096, 128, SMEM_BYTES>>>(atoms, adj, sel,
                                            b1, b2, wp, bp, out);
}